// round 2
// baseline (speedup 1.0000x reference)
#include <cuda_runtime.h>

#define CCH   192
#define HDIM  448
#define HWSZ  (448*448)
#define NHEAD 6
#define HD    32
#define NT    49      // tokens per window
#define TPAD  56      // padded token rows in smem buffers
#define CPAD  196     // padded channel stride (mult of 4; conflict-free f4 strided reads)
#define SROW  52      // score row stride / padded rows

// smem layout (floats): xs(ao) | qs(po) | ks | vs | Ws | scores | mreg
constexpr int SM_FLOATS = 4 * TPAD * CPAD + 32 * CPAD + SROW * SROW + 64;

__global__ __launch_bounds__(256, 1)
void swin_fused_kernel(const float* __restrict__ x,
                       const float* __restrict__ qkvW,
                       const float* __restrict__ qkvB,
                       const float* __restrict__ projW,
                       const float* __restrict__ projB,
                       const float* __restrict__ table,
                       float* __restrict__ out)
{
    extern __shared__ float sm[];
    float* xs = sm;                        // TPAD*CPAD   (reused as attention output ao)
    float* qs = xs + TPAD * CPAD;          // TPAD*CPAD   (reused as proj output po)
    float* ks = qs + TPAD * CPAD;
    float* vs = ks + TPAD * CPAD;
    float* Ws = vs + TPAD * CPAD;          // 32*CPAD weight stage
    float* sc = Ws + 32 * CPAD;            // SROW*SROW scores
    int*   mreg = (int*)(sc + SROW * SROW);

    const int tid  = threadIdx.x;
    const int lane = tid & 31;
    const int warp = tid >> 5;
    const int wy = blockIdx.x >> 6;
    const int wx = blockIdx.x & 63;

    // region buckets for the shift mask (on the shifted frame)
    if (tid < NT) {
        int r = tid / 7, cc = tid - (tid / 7) * 7;
        int hs = wy * 7 + r, ws = wx * 7 + cc;
        int rb = (hs >= 441) + (hs >= 445);
        int cb = (ws >= 441) + (ws >= 445);
        mreg[tid] = rb * 3 + cb;
    }

    // ---- gather shifted window into xs[tok][c] ----
    for (int idx = tid; idx < CCH * NT; idx += 256) {
        int c = idx / NT, t = idx - c * NT;
        int r = t / 7, cc = t - r * 7;
        int h = wy * 7 + r + 3; if (h >= HDIM) h -= HDIM;
        int w = wx * 7 + cc + 3; if (w >= HDIM) w -= HDIM;
        xs[t * CPAD + c] = x[c * HWSZ + h * HDIM + w];
    }
    __syncthreads();

    const int ocl = lane;   // output-channel lane within 32-wide stage
    const int tl  = warp;   // token lane (8 groups)

    // ---- QKV GEMM: 18 stages of 32 output channels ----
    for (int ob = 0; ob < 18; ob++) {
        for (int i = tid; i < 32 * CCH; i += 256) {
            int rr = i / CCH, col = i - rr * CCH;
            Ws[rr * CPAD + col] = qkvW[(ob * 32 + rr) * CCH + col];
        }
        __syncthreads();

        float acc[7] = {0.f, 0.f, 0.f, 0.f, 0.f, 0.f, 0.f};
        const float* wrow = Ws + ocl * CPAD;
        #pragma unroll 4
        for (int c = 0; c < CCH; c += 4) {
            const float4 w4 = *(const float4*)(wrow + c);
            #pragma unroll
            for (int j = 0; j < 7; j++) {
                const float4 x4 = *(const float4*)(xs + (tl + 8 * j) * CPAD + c);
                acc[j] += x4.x * w4.x;
                acc[j] += x4.y * w4.y;
                acc[j] += x4.z * w4.z;
                acc[j] += x4.w * w4.w;
            }
        }
        int oc = ob * 32 + ocl;
        float b = qkvB[oc];
        float scl = 1.0f; float* dst; int ch;
        if (oc < 192)      { dst = qs; ch = oc;       scl = 0.17677669529663687f; } // hd^-0.5
        else if (oc < 384) { dst = ks; ch = oc - 192; }
        else               { dst = vs; ch = oc - 384; }
        #pragma unroll
        for (int j = 0; j < 7; j++)
            dst[(tl + 8 * j) * CPAD + ch] = (acc[j] + b) * scl;
        __syncthreads();
    }

    // ---- attention per head ----
    for (int h = 0; h < NHEAD; h++) {
        const int kb = h * HD;
        // scores: warp handles 4 query rows; lane covers j and j+32
        for (int ig = warp; ig < 13; ig += 8) {
            int i0 = ig * 4;
            float a[4][2] = {{0.f,0.f},{0.f,0.f},{0.f,0.f},{0.f,0.f}};
            const int j2 = lane + 32;
            const bool j2v = (j2 < NT);
            #pragma unroll
            for (int d = 0; d < HD; d += 4) {
                float4 k0 = *(const float4*)(ks + lane * CPAD + kb + d);
                float4 k1 = make_float4(0.f, 0.f, 0.f, 0.f);
                if (j2v) k1 = *(const float4*)(ks + j2 * CPAD + kb + d);
                #pragma unroll
                for (int ii = 0; ii < 4; ii++) {
                    const float4 q4 = *(const float4*)(qs + (i0 + ii) * CPAD + kb + d);
                    a[ii][0] += q4.x * k0.x + q4.y * k0.y + q4.z * k0.z + q4.w * k0.w;
                    a[ii][1] += q4.x * k1.x + q4.y * k1.y + q4.z * k1.z + q4.w * k1.w;
                }
            }
            #pragma unroll
            for (int ii = 0; ii < 4; ii++) {
                int i = i0 + ii;
                if (i >= NT) break;
                int ri = i / 7, ci = i - ri * 7;
                int mi = mreg[i];
                #pragma unroll
                for (int jj = 0; jj < 2; jj++) {
                    int j = lane + jj * 32;
                    if (j >= NT) continue;
                    int rj = j / 7, cj = j - rj * 7;
                    int rel = (ri - rj) + (ci - cj);
                    if (rel < 0) rel += 169;            // wraparound gather quirk
                    float bi = table[rel * NHEAD + h];
                    float msk = (mi == mreg[j]) ? 0.0f : -100.0f;
                    sc[i * SROW + j] = a[ii][jj] + bi + msk;
                }
            }
        }
        __syncthreads();

        // softmax per row (warp per row)
        for (int i = warp; i < NT; i += 8) {
            float v0 = sc[i * SROW + lane];
            float v1 = (lane + 32 < NT) ? sc[i * SROW + lane + 32] : -1e30f;
            float mx = fmaxf(v0, v1);
            #pragma unroll
            for (int off = 16; off; off >>= 1)
                mx = fmaxf(mx, __shfl_xor_sync(0xffffffffu, mx, off));
            float e0 = __expf(v0 - mx);
            float e1 = (lane + 32 < NT) ? __expf(v1 - mx) : 0.0f;
            float sum = e0 + e1;
            #pragma unroll
            for (int off = 16; off; off >>= 1)
                sum += __shfl_xor_sync(0xffffffffu, sum, off);
            float inv = 1.0f / sum;
            sc[i * SROW + lane] = e0 * inv;
            if (lane + 32 < NT) sc[i * SROW + lane + 32] = e1 * inv;
        }
        __syncthreads();

        // P @ V : warp handles 4 rows, lane = head dim
        {
            const int vb = kb + lane;
            for (int ig = warp; ig < 13; ig += 8) {
                int i0 = ig * 4;
                float acc2[4] = {0.f, 0.f, 0.f, 0.f};
                #pragma unroll 4
                for (int j = 0; j < 48; j += 4) {
                    float4 p0 = *(const float4*)(sc + (i0 + 0) * SROW + j);
                    float4 p1 = *(const float4*)(sc + (i0 + 1) * SROW + j);
                    float4 p2 = *(const float4*)(sc + (i0 + 2) * SROW + j);
                    float4 p3 = *(const float4*)(sc + (i0 + 3) * SROW + j);
                    #pragma unroll
                    for (int jj = 0; jj < 4; jj++) {
                        float vv = vs[(j + jj) * CPAD + vb];
                        acc2[0] += ((const float*)&p0)[jj] * vv;
                        acc2[1] += ((const float*)&p1)[jj] * vv;
                        acc2[2] += ((const float*)&p2)[jj] * vv;
                        acc2[3] += ((const float*)&p3)[jj] * vv;
                    }
                }
                {   // tail j = 48
                    float vv = vs[48 * CPAD + vb];
                    acc2[0] += sc[(i0 + 0) * SROW + 48] * vv;
                    acc2[1] += sc[(i0 + 1) * SROW + 48] * vv;
                    acc2[2] += sc[(i0 + 2) * SROW + 48] * vv;
                    acc2[3] += sc[(i0 + 3) * SROW + 48] * vv;
                }
                #pragma unroll
                for (int ii = 0; ii < 4; ii++)
                    if (i0 + ii < NT) xs[(i0 + ii) * CPAD + kb + lane] = acc2[ii];
            }
        }
        __syncthreads();
    }

    // ---- proj GEMM: 6 stages of 32 output channels (reads ao=xs, writes po=qs) ----
    for (int ob = 0; ob < 6; ob++) {
        for (int i = tid; i < 32 * CCH; i += 256) {
            int rr = i / CCH, col = i - rr * CCH;
            Ws[rr * CPAD + col] = projW[(ob * 32 + rr) * CCH + col];
        }
        __syncthreads();

        float acc[7] = {0.f, 0.f, 0.f, 0.f, 0.f, 0.f, 0.f};
        const float* wrow = Ws + ocl * CPAD;
        #pragma unroll 4
        for (int c = 0; c < CCH; c += 4) {
            const float4 w4 = *(const float4*)(wrow + c);
            #pragma unroll
            for (int j = 0; j < 7; j++) {
                const float4 x4 = *(const float4*)(xs + (tl + 8 * j) * CPAD + c);
                acc[j] += x4.x * w4.x;
                acc[j] += x4.y * w4.y;
                acc[j] += x4.z * w4.z;
                acc[j] += x4.w * w4.w;
            }
        }
        int oc = ob * 32 + ocl;
        float b = projB[oc];
        #pragma unroll
        for (int j = 0; j < 7; j++)
            qs[(tl + 8 * j) * CPAD + oc] = acc[j] + b;
        __syncthreads();
    }

    // ---- scatter with reverse shift (same index map as gather) ----
    for (int idx = tid; idx < CCH * NT; idx += 256) {
        int c = idx / NT, t = idx - c * NT;
        int r = t / 7, cc = t - r * 7;
        int h = wy * 7 + r + 3; if (h >= HDIM) h -= HDIM;
        int w = wx * 7 + cc + 3; if (w >= HDIM) w -= HDIM;
        out[c * HWSZ + h * HDIM + w] = qs[t * CPAD + c];
    }
}

extern "C" void kernel_launch(void* const* d_in, const int* in_sizes, int n_in,
                              void* d_out, int out_size) {
    const float* x     = (const float*)d_in[0];
    const float* qkvW  = (const float*)d_in[1];
    const float* qkvB  = (const float*)d_in[2];
    const float* projW = (const float*)d_in[3];
    const float* projB = (const float*)d_in[4];
    const float* table = (const float*)d_in[5];
    float* out = (float*)d_out;

    const size_t smem = (size_t)SM_FLOATS * sizeof(float);   // ~211.8 KB
    cudaFuncSetAttribute(swin_fused_kernel,
                         cudaFuncAttributeMaxDynamicSharedMemorySize, (int)smem);
    swin_fused_kernel<<<4096, 256, smem>>>(x, qkvW, qkvB, projW, projB, table, out);
}

// round 3
// speedup vs baseline: 1.2638x; 1.2638x over previous
#include <cuda_runtime.h>

#define CCH   192
#define HDIM  448
#define HWSZ  (448*448)
#define NHEAD 6
#define HD    32
#define NT    49      // tokens per window
#define TPAD  56      // padded token rows in smem buffers
#define CPAD  196     // padded channel stride (conflict-free f4 strided reads)
#define SROW  52      // score row stride

// smem (floats): xs(ao) | qs(po) | ks | vs | Ws(64 rows; scores overlaid) | mreg
constexpr int SM_FLOATS = 4 * TPAD * CPAD + 64 * CPAD + 64;

typedef unsigned long long u64;

__device__ __forceinline__ u64 fma2(u64 a, u64 b, u64 c) {
    u64 d;
    asm("fma.rn.f32x2 %0, %1, %2, %3;" : "=l"(d) : "l"(a), "l"(b), "l"(c));
    return d;
}
__device__ __forceinline__ float lohi_sum(u64 v) {
    float2 f = *reinterpret_cast<float2*>(&v);
    return f.x + f.y;
}

__global__ __launch_bounds__(256, 1)
void swin_fused_kernel(const float* __restrict__ x,
                       const float* __restrict__ qkvW,
                       const float* __restrict__ qkvB,
                       const float* __restrict__ projW,
                       const float* __restrict__ projB,
                       const float* __restrict__ table,
                       float* __restrict__ out)
{
    extern __shared__ float sm[];
    float* xs = sm;                        // TPAD*CPAD (reused as attention output)
    float* qs = xs + TPAD * CPAD;          // TPAD*CPAD (reused as proj output)
    float* ks = qs + TPAD * CPAD;
    float* vs = ks + TPAD * CPAD;
    float* Ws = vs + TPAD * CPAD;          // 64*CPAD weight stage
    float* sc = Ws;                        // scores overlay Ws (disjoint in time)
    int*   mreg = (int*)(Ws + 64 * CPAD);

    const int tid  = threadIdx.x;
    const int lane = tid & 31;
    const int warp = tid >> 5;
    const int wy = blockIdx.x >> 6;
    const int wx = blockIdx.x & 63;

    // region buckets for the shift mask (on the shifted frame)
    if (tid < NT) {
        int r = tid / 7, cc = tid - (tid / 7) * 7;
        int hs = wy * 7 + r, ws = wx * 7 + cc;
        int rb = (hs >= 441) + (hs >= 445);
        int cb = (ws >= 441) + (ws >= 445);
        mreg[tid] = rb * 3 + cb;
    }

    // ---- gather shifted window into xs[tok][c] ----
    for (int idx = tid; idx < CCH * NT; idx += 256) {
        int c = idx / NT, t = idx - c * NT;
        int r = t / 7, cc = t - r * 7;
        int h = wy * 7 + r + 3; if (h >= HDIM) h -= HDIM;
        int w = wx * 7 + cc + 3; if (w >= HDIM) w -= HDIM;
        xs[t * CPAD + c] = x[c * HWSZ + h * HDIM + w];
    }
    __syncthreads();

    const int tg = warp;   // token group: tokens tg + 8j, j=0..6

    // ---- QKV GEMM: 9 stages of 64 output channels, U=2 per thread, f32x2 ----
    for (int ob = 0; ob < 9; ob++) {
        for (int i = tid; i < 64 * CCH; i += 256) {
            int rr = i / CCH, col = i - rr * CCH;
            Ws[rr * CPAD + col] = qkvW[(ob * 64 + rr) * CCH + col];
        }
        __syncthreads();

        u64 acc0[7], acc1[7];
        #pragma unroll
        for (int j = 0; j < 7; j++) { acc0[j] = 0ULL; acc1[j] = 0ULL; }
        const float* w0p = Ws + lane * CPAD;
        const float* w1p = Ws + (lane + 32) * CPAD;
        #pragma unroll 2
        for (int c = 0; c < CCH; c += 4) {
            const ulonglong2 w0 = *(const ulonglong2*)(w0p + c);
            const ulonglong2 w1 = *(const ulonglong2*)(w1p + c);
            #pragma unroll
            for (int j = 0; j < 7; j++) {
                const ulonglong2 xv = *(const ulonglong2*)(xs + (tg + 8 * j) * CPAD + c);
                acc0[j] = fma2(xv.x, w0.x, acc0[j]);
                acc0[j] = fma2(xv.y, w0.y, acc0[j]);
                acc1[j] = fma2(xv.x, w1.x, acc1[j]);
                acc1[j] = fma2(xv.y, w1.y, acc1[j]);
            }
        }

        #pragma unroll
        for (int u = 0; u < 2; u++) {
            int oc = ob * 64 + lane + u * 32;
            u64* acc = u ? acc1 : acc0;
            float b = qkvB[oc];
            float scl = 1.0f; float* dst; int ch;
            if (oc < 192)      { dst = qs; ch = oc;       scl = 0.17677669529663687f; }
            else if (oc < 384) { dst = ks; ch = oc - 192; }
            else               { dst = vs; ch = oc - 384; }
            #pragma unroll
            for (int j = 0; j < 7; j++)
                dst[(tg + 8 * j) * CPAD + ch] = (lohi_sum(acc[j]) + b) * scl;
        }
        __syncthreads();
    }

    // ---- attention per head ----
    for (int h = 0; h < NHEAD; h++) {
        const int kb = h * HD;
        // scores: warp handles 4 query rows; lane covers j and j+32 (f32x2 accum)
        for (int ig = warp; ig < 13; ig += 8) {
            int i0 = ig * 4;
            u64 a2[4][2];
            #pragma unroll
            for (int ii = 0; ii < 4; ii++) { a2[ii][0] = 0ULL; a2[ii][1] = 0ULL; }
            const int j2 = lane + 32;
            const bool j2v = (j2 < NT);
            #pragma unroll
            for (int d = 0; d < HD; d += 4) {
                ulonglong2 k0 = *(const ulonglong2*)(ks + lane * CPAD + kb + d);
                ulonglong2 k1;
                if (j2v) k1 = *(const ulonglong2*)(ks + j2 * CPAD + kb + d);
                else     { k1.x = 0ULL; k1.y = 0ULL; }
                #pragma unroll
                for (int ii = 0; ii < 4; ii++) {
                    const ulonglong2 q2 = *(const ulonglong2*)(qs + (i0 + ii) * CPAD + kb + d);
                    a2[ii][0] = fma2(q2.x, k0.x, a2[ii][0]);
                    a2[ii][0] = fma2(q2.y, k0.y, a2[ii][0]);
                    a2[ii][1] = fma2(q2.x, k1.x, a2[ii][1]);
                    a2[ii][1] = fma2(q2.y, k1.y, a2[ii][1]);
                }
            }
            #pragma unroll
            for (int ii = 0; ii < 4; ii++) {
                int i = i0 + ii;
                if (i >= NT) break;
                int ri = i / 7, ci = i - ri * 7;
                int mi = mreg[i];
                #pragma unroll
                for (int jj = 0; jj < 2; jj++) {
                    int j = lane + jj * 32;
                    if (j >= NT) continue;
                    int rj = j / 7, cj = j - rj * 7;
                    int rel = (ri - rj) + (ci - cj);
                    if (rel < 0) rel += 169;            // wraparound gather quirk
                    float bi = table[rel * NHEAD + h];
                    float msk = (mi == mreg[j]) ? 0.0f : -100.0f;
                    sc[i * SROW + j] = lohi_sum(a2[ii][jj]) + bi + msk;
                }
            }
        }
        __syncthreads();

        // softmax per row (warp per row)
        for (int i = warp; i < NT; i += 8) {
            float v0 = sc[i * SROW + lane];
            float v1 = (lane + 32 < NT) ? sc[i * SROW + lane + 32] : -1e30f;
            float mx = fmaxf(v0, v1);
            #pragma unroll
            for (int off = 16; off; off >>= 1)
                mx = fmaxf(mx, __shfl_xor_sync(0xffffffffu, mx, off));
            float e0 = __expf(v0 - mx);
            float e1 = (lane + 32 < NT) ? __expf(v1 - mx) : 0.0f;
            float sum = e0 + e1;
            #pragma unroll
            for (int off = 16; off; off >>= 1)
                sum += __shfl_xor_sync(0xffffffffu, sum, off);
            float inv = 1.0f / sum;
            sc[i * SROW + lane] = e0 * inv;
            if (lane + 32 < NT) sc[i * SROW + lane + 32] = e1 * inv;
        }
        __syncthreads();

        // P @ V : warp handles 4 rows, lane = head dim
        {
            const int vb = kb + lane;
            for (int ig = warp; ig < 13; ig += 8) {
                int i0 = ig * 4;
                float acc2[4] = {0.f, 0.f, 0.f, 0.f};
                #pragma unroll 4
                for (int j = 0; j < 48; j += 4) {
                    float4 p0 = *(const float4*)(sc + (i0 + 0) * SROW + j);
                    float4 p1 = *(const float4*)(sc + (i0 + 1) * SROW + j);
                    float4 p2 = *(const float4*)(sc + (i0 + 2) * SROW + j);
                    float4 p3 = *(const float4*)(sc + (i0 + 3) * SROW + j);
                    #pragma unroll
                    for (int jj = 0; jj < 4; jj++) {
                        float vv = vs[(j + jj) * CPAD + vb];
                        acc2[0] += ((const float*)&p0)[jj] * vv;
                        acc2[1] += ((const float*)&p1)[jj] * vv;
                        acc2[2] += ((const float*)&p2)[jj] * vv;
                        acc2[3] += ((const float*)&p3)[jj] * vv;
                    }
                }
                {   // tail j = 48
                    float vv = vs[48 * CPAD + vb];
                    acc2[0] += sc[(i0 + 0) * SROW + 48] * vv;
                    acc2[1] += sc[(i0 + 1) * SROW + 48] * vv;
                    acc2[2] += sc[(i0 + 2) * SROW + 48] * vv;
                    acc2[3] += sc[(i0 + 3) * SROW + 48] * vv;
                }
                #pragma unroll
                for (int ii = 0; ii < 4; ii++)
                    if (i0 + ii < NT) xs[(i0 + ii) * CPAD + kb + lane] = acc2[ii];
            }
        }
        __syncthreads();
    }

    // ---- proj GEMM: 3 stages of 64 output channels (reads ao=xs, writes po=qs) ----
    for (int ob = 0; ob < 3; ob++) {
        for (int i = tid; i < 64 * CCH; i += 256) {
            int rr = i / CCH, col = i - rr * CCH;
            Ws[rr * CPAD + col] = projW[(ob * 64 + rr) * CCH + col];
        }
        __syncthreads();

        u64 acc0[7], acc1[7];
        #pragma unroll
        for (int j = 0; j < 7; j++) { acc0[j] = 0ULL; acc1[j] = 0ULL; }
        const float* w0p = Ws + lane * CPAD;
        const float* w1p = Ws + (lane + 32) * CPAD;
        #pragma unroll 2
        for (int c = 0; c < CCH; c += 4) {
            const ulonglong2 w0 = *(const ulonglong2*)(w0p + c);
            const ulonglong2 w1 = *(const ulonglong2*)(w1p + c);
            #pragma unroll
            for (int j = 0; j < 7; j++) {
                const ulonglong2 xv = *(const ulonglong2*)(xs + (tg + 8 * j) * CPAD + c);
                acc0[j] = fma2(xv.x, w0.x, acc0[j]);
                acc0[j] = fma2(xv.y, w0.y, acc0[j]);
                acc1[j] = fma2(xv.x, w1.x, acc1[j]);
                acc1[j] = fma2(xv.y, w1.y, acc1[j]);
            }
        }

        #pragma unroll
        for (int u = 0; u < 2; u++) {
            int oc = ob * 64 + lane + u * 32;
            u64* acc = u ? acc1 : acc0;
            float b = projB[oc];
            #pragma unroll
            for (int j = 0; j < 7; j++)
                qs[(tg + 8 * j) * CPAD + oc] = lohi_sum(acc[j]) + b;
        }
        __syncthreads();
    }

    // ---- scatter with reverse shift (same index map as gather) ----
    for (int idx = tid; idx < CCH * NT; idx += 256) {
        int c = idx / NT, t = idx - c * NT;
        int r = t / 7, cc = t - r * 7;
        int h = wy * 7 + r + 3; if (h >= HDIM) h -= HDIM;
        int w = wx * 7 + cc + 3; if (w >= HDIM) w -= HDIM;
        out[c * HWSZ + h * HDIM + w] = qs[t * CPAD + c];
    }
}

extern "C" void kernel_launch(void* const* d_in, const int* in_sizes, int n_in,
                              void* d_out, int out_size) {
    const float* x     = (const float*)d_in[0];
    const float* qkvW  = (const float*)d_in[1];
    const float* qkvB  = (const float*)d_in[2];
    const float* projW = (const float*)d_in[3];
    const float* projB = (const float*)d_in[4];
    const float* table = (const float*)d_in[5];
    float* out = (float*)d_out;

    const size_t smem = (size_t)SM_FLOATS * sizeof(float);   // ~226 KB
    cudaFuncSetAttribute(swin_fused_kernel,
                         cudaFuncAttributeMaxDynamicSharedMemorySize, (int)smem);
    swin_fused_kernel<<<4096, 256, smem>>>(x, qkvW, qkvB, projW, projB, table, out);
}

// round 4
// speedup vs baseline: 1.4175x; 1.1216x over previous
#include <cuda_runtime.h>

#define CCH   192
#define HDIM  448
#define HWSZ  (448*448)
#define NHEAD 6
#define HD    32
#define NT    49      // tokens per window
#define CPAD  196     // padded channel stride (conflict-free f4 strided reads)
#define SROW  52      // score row stride
#define SCOFF 2560    // offset between the two per-head score buffers

// smem (floats): xs(56 rows) | qs | ks | vs (49 rows each) | Ws(64; scores overlay) | part | mreg
constexpr int XS_F = 56 * CPAD;          // 10976 (GEMM reads tokens up to 55)
constexpr int BUF_F = NT * CPAD;         // 9604
constexpr int WS_F = 64 * CPAD;          // 12544
constexpr int PART_F = NT * 64 + 48;     // 3184 (pad)
constexpr int SM_FLOATS = XS_F + 3 * BUF_F + WS_F + PART_F + 64;

typedef unsigned long long u64;

__device__ __forceinline__ u64 fma2(u64 a, u64 b, u64 c) {
    u64 d;
    asm("fma.rn.f32x2 %0, %1, %2, %3;" : "=l"(d) : "l"(a), "l"(b), "l"(c));
    return d;
}
__device__ __forceinline__ float lohi_sum(u64 v) {
    float2 f = *reinterpret_cast<float2*>(&v);
    return f.x + f.y;
}

__global__ __launch_bounds__(512, 1)
void swin_fused_kernel(const float* __restrict__ x,
                       const float* __restrict__ qkvW,
                       const float* __restrict__ qkvB,
                       const float* __restrict__ projW,
                       const float* __restrict__ projB,
                       const float* __restrict__ table,
                       float* __restrict__ out)
{
    extern __shared__ float sm[];
    float* xs = sm;                        // 56 rows (reused as attention output)
    float* qs = xs + XS_F;                 // 49 rows (reused as proj output)
    float* ks = qs + BUF_F;
    float* vs = ks + BUF_F;
    float* Ws = vs + BUF_F;                // 64*CPAD weight stage
    float* sc = Ws;                        // two score buffers overlay Ws
    float* part = Ws + WS_F;               // split-K partials: [tok][oc64]
    int*   mreg = (int*)(part + PART_F);

    const int tid  = threadIdx.x;
    const int lane = tid & 31;
    const int warp = tid >> 5;
    const int w8   = warp & 7;             // token group / row group
    const int half = warp >> 3;            // split-K half (c range / head parity)
    const int wy = blockIdx.x >> 6;
    const int wx = blockIdx.x & 63;

    // region buckets for the shift mask (on the shifted frame)
    if (tid < NT) {
        int r = tid / 7, cc = tid - (tid / 7) * 7;
        int hs = wy * 7 + r, ws = wx * 7 + cc;
        int rb = (hs >= 441) + (hs >= 445);
        int cb = (ws >= 441) + (ws >= 445);
        mreg[tid] = rb * 3 + cb;
    }

    // ---- gather shifted window into xs[tok][c] ----
    for (int idx = tid; idx < CCH * NT; idx += 512) {
        int c = idx / NT, t = idx - c * NT;
        int r = t / 7, cc = t - r * 7;
        int h = wy * 7 + r + 3; if (h >= HDIM) h -= HDIM;
        int w = wx * 7 + cc + 3; if (w >= HDIM) w -= HDIM;
        xs[t * CPAD + c] = x[c * HWSZ + h * HDIM + w];
    }
    __syncthreads();

    const int tg = w8;                 // tokens tg + 8j, j=0..6
    const int c0 = half * 96;          // split-K channel range [c0, c0+96)

    // ---- QKV GEMM: 9 stages of 64 oc, U=2 per thread, split-K over 2 warp-halves ----
    for (int ob = 0; ob < 9; ob++) {
        for (int i = tid; i < 64 * CCH; i += 512) {
            int rr = i / CCH, col = i - rr * CCH;
            Ws[rr * CPAD + col] = qkvW[(ob * 64 + rr) * CCH + col];
        }
        __syncthreads();

        u64 acc0[7], acc1[7];
        #pragma unroll
        for (int j = 0; j < 7; j++) { acc0[j] = 0ULL; acc1[j] = 0ULL; }
        const float* w0p = Ws + lane * CPAD;
        const float* w1p = Ws + (lane + 32) * CPAD;
        #pragma unroll 2
        for (int c = c0; c < c0 + 96; c += 4) {
            const ulonglong2 w0 = *(const ulonglong2*)(w0p + c);
            const ulonglong2 w1 = *(const ulonglong2*)(w1p + c);
            #pragma unroll
            for (int j = 0; j < 7; j++) {
                const ulonglong2 xv = *(const ulonglong2*)(xs + (tg + 8 * j) * CPAD + c);
                acc0[j] = fma2(xv.x, w0.x, acc0[j]);
                acc0[j] = fma2(xv.y, w0.y, acc0[j]);
                acc1[j] = fma2(xv.x, w1.x, acc1[j]);
                acc1[j] = fma2(xv.y, w1.y, acc1[j]);
            }
        }

        // half 1 publishes partials
        if (half == 1) {
            #pragma unroll
            for (int j = 0; j < 7; j++) {
                int t = tg + 8 * j;
                if (t < NT) {
                    part[t * 64 + lane]      = lohi_sum(acc0[j]);
                    part[t * 64 + lane + 32] = lohi_sum(acc1[j]);
                }
            }
        }
        __syncthreads();

        // half 0 reduces + writes
        if (half == 0) {
            #pragma unroll
            for (int u = 0; u < 2; u++) {
                int oc = ob * 64 + lane + u * 32;
                u64* acc = u ? acc1 : acc0;
                float b = qkvB[oc];
                float scl = 1.0f; float* dst; int ch;
                if (oc < 192)      { dst = qs; ch = oc;       scl = 0.17677669529663687f; }
                else if (oc < 384) { dst = ks; ch = oc - 192; }
                else               { dst = vs; ch = oc - 384; }
                #pragma unroll
                for (int j = 0; j < 7; j++) {
                    int t = tg + 8 * j;
                    if (t < NT) {
                        float v = lohi_sum(acc[j]) + part[t * 64 + lane + u * 32] + b;
                        dst[t * CPAD + ch] = v * scl;
                    }
                }
            }
        }
        __syncthreads();
    }

    // ---- attention: 3 passes, 2 heads per pass (one per warp-half) ----
    for (int hp = 0; hp < 3; hp++) {
        const int h  = hp * 2 + half;
        const int kb = h * HD;
        float* shc = sc + half * SCOFF;

        // scores: warp handles 4 query rows; lane covers j and j+32
        for (int ig = w8; ig < 13; ig += 8) {
            int i0 = ig * 4;
            u64 a2[4][2];
            #pragma unroll
            for (int ii = 0; ii < 4; ii++) { a2[ii][0] = 0ULL; a2[ii][1] = 0ULL; }
            const int j2 = lane + 32;
            const bool j2v = (j2 < NT);
            #pragma unroll
            for (int d = 0; d < HD; d += 4) {
                ulonglong2 k0 = *(const ulonglong2*)(ks + lane * CPAD + kb + d);
                ulonglong2 k1;
                if (j2v) k1 = *(const ulonglong2*)(ks + j2 * CPAD + kb + d);
                else     { k1.x = 0ULL; k1.y = 0ULL; }
                #pragma unroll
                for (int ii = 0; ii < 4; ii++) {
                    const ulonglong2 q2 = *(const ulonglong2*)(qs + (i0 + ii) * CPAD + kb + d);
                    a2[ii][0] = fma2(q2.x, k0.x, a2[ii][0]);
                    a2[ii][0] = fma2(q2.y, k0.y, a2[ii][0]);
                    a2[ii][1] = fma2(q2.x, k1.x, a2[ii][1]);
                    a2[ii][1] = fma2(q2.y, k1.y, a2[ii][1]);
                }
            }
            #pragma unroll
            for (int ii = 0; ii < 4; ii++) {
                int i = i0 + ii;
                if (i >= NT) break;
                int ri = i / 7, ci = i - ri * 7;
                int mi = mreg[i];
                #pragma unroll
                for (int jj = 0; jj < 2; jj++) {
                    int j = lane + jj * 32;
                    if (j >= NT) continue;
                    int rj = j / 7, cj = j - rj * 7;
                    int rel = (ri - rj) + (ci - cj);
                    if (rel < 0) rel += 169;            // wraparound gather quirk
                    float bi = table[rel * NHEAD + h];
                    float msk = (mi == mreg[j]) ? 0.0f : -100.0f;
                    shc[i * SROW + j] = lohi_sum(a2[ii][jj]) + bi + msk;
                }
            }
        }
        __syncthreads();

        // softmax per row (warp per row)
        for (int i = w8; i < NT; i += 8) {
            float v0 = shc[i * SROW + lane];
            float v1 = (lane + 32 < NT) ? shc[i * SROW + lane + 32] : -1e30f;
            float mx = fmaxf(v0, v1);
            #pragma unroll
            for (int off = 16; off; off >>= 1)
                mx = fmaxf(mx, __shfl_xor_sync(0xffffffffu, mx, off));
            float e0 = __expf(v0 - mx);
            float e1 = (lane + 32 < NT) ? __expf(v1 - mx) : 0.0f;
            float sum = e0 + e1;
            #pragma unroll
            for (int off = 16; off; off >>= 1)
                sum += __shfl_xor_sync(0xffffffffu, sum, off);
            float inv = 1.0f / sum;
            shc[i * SROW + lane] = e0 * inv;
            if (lane + 32 < NT) shc[i * SROW + lane + 32] = e1 * inv;
        }
        __syncthreads();

        // P @ V : warp handles 4 rows, lane = head dim
        {
            const int vb = kb + lane;
            for (int ig = w8; ig < 13; ig += 8) {
                int i0 = ig * 4;
                float acc2[4] = {0.f, 0.f, 0.f, 0.f};
                #pragma unroll 4
                for (int j = 0; j < 48; j += 4) {
                    float4 p0 = *(const float4*)(shc + (i0 + 0) * SROW + j);
                    float4 p1 = *(const float4*)(shc + (i0 + 1) * SROW + j);
                    float4 p2 = *(const float4*)(shc + (i0 + 2) * SROW + j);
                    float4 p3 = *(const float4*)(shc + (i0 + 3) * SROW + j);
                    #pragma unroll
                    for (int jj = 0; jj < 4; jj++) {
                        float vv = vs[(j + jj) * CPAD + vb];
                        acc2[0] += ((const float*)&p0)[jj] * vv;
                        acc2[1] += ((const float*)&p1)[jj] * vv;
                        acc2[2] += ((const float*)&p2)[jj] * vv;
                        acc2[3] += ((const float*)&p3)[jj] * vv;
                    }
                }
                {   // tail j = 48
                    float vv = vs[48 * CPAD + vb];
                    acc2[0] += shc[(i0 + 0) * SROW + 48] * vv;
                    acc2[1] += shc[(i0 + 1) * SROW + 48] * vv;
                    acc2[2] += shc[(i0 + 2) * SROW + 48] * vv;
                    acc2[3] += shc[(i0 + 3) * SROW + 48] * vv;
                }
                #pragma unroll
                for (int ii = 0; ii < 4; ii++)
                    if (i0 + ii < NT) xs[(i0 + ii) * CPAD + kb + lane] = acc2[ii];
            }
        }
        __syncthreads();
    }

    // ---- proj GEMM: 3 stages of 64 oc, split-K (reads ao=xs, writes po=qs) ----
    for (int ob = 0; ob < 3; ob++) {
        for (int i = tid; i < 64 * CCH; i += 512) {
            int rr = i / CCH, col = i - rr * CCH;
            Ws[rr * CPAD + col] = projW[(ob * 64 + rr) * CCH + col];
        }
        __syncthreads();

        u64 acc0[7], acc1[7];
        #pragma unroll
        for (int j = 0; j < 7; j++) { acc0[j] = 0ULL; acc1[j] = 0ULL; }
        const float* w0p = Ws + lane * CPAD;
        const float* w1p = Ws + (lane + 32) * CPAD;
        #pragma unroll 2
        for (int c = c0; c < c0 + 96; c += 4) {
            const ulonglong2 w0 = *(const ulonglong2*)(w0p + c);
            const ulonglong2 w1 = *(const ulonglong2*)(w1p + c);
            #pragma unroll
            for (int j = 0; j < 7; j++) {
                const ulonglong2 xv = *(const ulonglong2*)(xs + (tg + 8 * j) * CPAD + c);
                acc0[j] = fma2(xv.x, w0.x, acc0[j]);
                acc0[j] = fma2(xv.y, w0.y, acc0[j]);
                acc1[j] = fma2(xv.x, w1.x, acc1[j]);
                acc1[j] = fma2(xv.y, w1.y, acc1[j]);
            }
        }

        if (half == 1) {
            #pragma unroll
            for (int j = 0; j < 7; j++) {
                int t = tg + 8 * j;
                if (t < NT) {
                    part[t * 64 + lane]      = lohi_sum(acc0[j]);
                    part[t * 64 + lane + 32] = lohi_sum(acc1[j]);
                }
            }
        }
        __syncthreads();

        if (half == 0) {
            #pragma unroll
            for (int u = 0; u < 2; u++) {
                int oc = ob * 64 + lane + u * 32;
                u64* acc = u ? acc1 : acc0;
                float b = projB[oc];
                #pragma unroll
                for (int j = 0; j < 7; j++) {
                    int t = tg + 8 * j;
                    if (t < NT)
                        qs[t * CPAD + oc] = lohi_sum(acc[j]) + part[t * 64 + lane + u * 32] + b;
                }
            }
        }
        __syncthreads();
    }

    // ---- scatter with reverse shift (same index map as gather) ----
    for (int idx = tid; idx < CCH * NT; idx += 512) {
        int c = idx / NT, t = idx - c * NT;
        int r = t / 7, cc = t - r * 7;
        int h = wy * 7 + r + 3; if (h >= HDIM) h -= HDIM;
        int w = wx * 7 + cc + 3; if (w >= HDIM) w -= HDIM;
        out[c * HWSZ + h * HDIM + w] = qs[t * CPAD + c];
    }
}

extern "C" void kernel_launch(void* const* d_in, const int* in_sizes, int n_in,
                              void* d_out, int out_size) {
    const float* x     = (const float*)d_in[0];
    const float* qkvW  = (const float*)d_in[1];
    const float* qkvB  = (const float*)d_in[2];
    const float* projW = (const float*)d_in[3];
    const float* projB = (const float*)d_in[4];
    const float* table = (const float*)d_in[5];
    float* out = (float*)d_out;

    const size_t smem = (size_t)SM_FLOATS * sizeof(float);   // ~224 KB
    cudaFuncSetAttribute(swin_fused_kernel,
                         cudaFuncAttributeMaxDynamicSharedMemorySize, (int)smem);
    swin_fused_kernel<<<4096, 512, smem>>>(x, qkvW, qkvB, projW, projB, table, out);
}

// round 7
// speedup vs baseline: 2.6573x; 1.8746x over previous
#include <cuda_runtime.h>
#include <cuda_bf16.h>
#include <cstdint>

#define NWIN  4096
#define NPAIR 2048
#define CCH   192
#define HDIM  448
#define HWSZ  (448*448)
#define NHEAD 6
#define HD    32
#define NT    49
#define CPAD  196
#define SROW  52
#define SCOFF 2816     // per-half score buffer (covers speculative reads to row 51)
#define XST   200      // bf16 row stride for mma tiles (400B: conflict-free ldmatrix)

// ---- device scratch ----
__device__ __align__(16) float g_q[(size_t)NWIN * NT * CCH];
__device__ __align__(16) float g_k[(size_t)NWIN * NT * CCH];
__device__ __align__(16) float g_v[(size_t)NWIN * NT * CCH];
__device__ __align__(16) __nv_bfloat16 g_qkvw[2 * 576 * 192];            // [split][oc][c]
__device__ __align__(16) __nv_bfloat16 g_projw[2 * 192 * 192];           // [split][oc][c]
__device__ __align__(16) __nv_bfloat16 g_ao[(size_t)NPAIR * 2 * 128 * XST]; // [pair][split][row][c]

// ---- helpers ----
__device__ __forceinline__ uint32_t smem_u32(const void* p) {
    uint32_t a;
    asm("{ .reg .u64 t; cvta.to.shared.u64 t, %1; cvt.u32.u64 %0, t; }" : "=r"(a) : "l"(p));
    return a;
}
#define LDSM4(r, a) asm volatile("ldmatrix.sync.aligned.m8n8.x4.shared.b16 {%0,%1,%2,%3}, [%4];" \
    : "=r"((r)[0]), "=r"((r)[1]), "=r"((r)[2]), "=r"((r)[3]) : "r"(a))
#define LDSM2(r, a) asm volatile("ldmatrix.sync.aligned.m8n8.x2.shared.b16 {%0,%1}, [%2];" \
    : "=r"((r)[0]), "=r"((r)[1]) : "r"(a))
#define MMA_BF16(d, A, B) asm volatile( \
    "mma.sync.aligned.m16n8k16.row.col.f32.bf16.bf16.f32 " \
    "{%0,%1,%2,%3}, {%4,%5,%6,%7}, {%8,%9}, {%0,%1,%2,%3};" \
    : "+f"((d)[0]), "+f"((d)[1]), "+f"((d)[2]), "+f"((d)[3]) \
    : "r"((A)[0]), "r"((A)[1]), "r"((A)[2]), "r"((A)[3]), "r"((B)[0]), "r"((B)[1]))

__device__ __forceinline__ void bf16_split(float v, __nv_bfloat16& hi, __nv_bfloat16& lo) {
    hi = __float2bfloat16(v);
    lo = __float2bfloat16(v - __bfloat162float(hi));
}

// ============================================================================
// Kernel 0: weight prep (fp32 -> bf16 hi/lo, dense row-major)
// ============================================================================
__global__ void prep_kernel(const float* __restrict__ qkvW, const float* __restrict__ projW) {
    int i = blockIdx.x * blockDim.x + threadIdx.x;
    if (i < 576 * 192) {
        __nv_bfloat16 hi, lo; bf16_split(qkvW[i], hi, lo);
        g_qkvw[i] = hi; g_qkvw[576 * 192 + i] = lo;
    } else {
        i -= 576 * 192;
        if (i < 192 * 192) {
            __nv_bfloat16 hi, lo; bf16_split(projW[i], hi, lo);
            g_projw[i] = hi; g_projw[192 * 192 + i] = lo;
        }
    }
}

// ============================================================================
// Kernel 1: QKV GEMM (mma.sync bf16 3-product split), M=128 = 2 windows
// ============================================================================
// smem bytes: Xh 51200 | Xl 51200 | Wh 38400 | Wl 38400 = 179200
#define QKV_SMEM 179200

__global__ __launch_bounds__(512, 1)
void qkv_kernel(const float* __restrict__ x, const float* __restrict__ qkvB)
{
    extern __shared__ char smem[];
    __nv_bfloat16* Xh = (__nv_bfloat16*)smem;
    __nv_bfloat16* Xl = (__nv_bfloat16*)(smem + 51200);
    __nv_bfloat16* Wh = (__nv_bfloat16*)(smem + 102400);
    __nv_bfloat16* Wl = (__nv_bfloat16*)(smem + 140800);
    const uint32_t sb = smem_u32(smem);
    const int tid = threadIdx.x, lane = tid & 31, warp = tid >> 5;
    const int pair = blockIdx.x;
    const int mw = warp & 3, nw = warp >> 2;

    // gather 2 shifted windows, bf16-split
    for (int idx = tid; idx < 2 * NT * CCH; idx += 512) {
        int wl_ = idx / (NT * CCH), rem = idx - wl_ * NT * CCH;
        int c = rem / NT, t = rem - c * NT;
        int win = pair * 2 + wl_, wy = win >> 6, wx = win & 63;
        int r = t / 7, cc = t - r * 7;
        int h = wy * 7 + r + 3; if (h >= HDIM) h -= HDIM;
        int w = wx * 7 + cc + 3; if (w >= HDIM) w -= HDIM;
        __nv_bfloat16 hi, lo; bf16_split(x[c * HWSZ + h * HDIM + w], hi, lo);
        int off = (wl_ * 64 + t) * XST + c;
        Xh[off] = hi; Xl[off] = lo;
    }
    // zero-pad rows 49..63, 113..127
    for (int idx = tid; idx < 30 * CCH; idx += 512) {
        int pr = idx / CCH, c = idx - pr * CCH;
        int row = (pr < 15) ? (49 + pr) : (98 + pr);
        int off = row * XST + c;
        Xh[off] = __float2bfloat16(0.f); Xl[off] = __float2bfloat16(0.f);
    }
    __syncthreads();

    // ldmatrix base offsets (bytes)
    const uint32_t aoffh = sb +          (uint32_t)(mw * 32 + (lane & 15)) * (XST * 2) + (lane >> 4) * 16;
    const uint32_t aoffl = aoffh + 51200;
    const uint32_t boffh = sb + 102400 + (uint32_t)(nw * 24 + (lane & 7)) * (XST * 2) + ((lane >> 3) & 1) * 16;
    const uint32_t boffl = boffh + 38400;

    for (int s = 0; s < 6; s++) {
        // stage 96 output rows of weights (hi+lo)
        for (int i = tid; i < 4608; i += 512) {
            int split = i >= 2304, j = i - split * 2304;
            int r = j / 24, p = j - r * 24;
            __nv_bfloat16* dst = split ? Wl : Wh;
            ((uint4*)(dst + r * XST))[p] =
                ((const uint4*)(g_qkvw + split * (576 * 192) + (s * 96 + r) * 192))[p];
        }
        __syncthreads();

        float acc[2][3][4];
        #pragma unroll
        for (int a = 0; a < 2; a++)
            #pragma unroll
            for (int b = 0; b < 3; b++)
                #pragma unroll
                for (int e = 0; e < 4; e++) acc[a][b][e] = 0.f;

        #pragma unroll 2
        for (int k = 0; k < 12; k++) {
            uint32_t ah[2][4], al[2][4], bh[3][2], bl[3][2];
            #pragma unroll
            for (int mt = 0; mt < 2; mt++) {
                LDSM4(ah[mt], aoffh + mt * 16 * (XST * 2) + k * 32);
                LDSM4(al[mt], aoffl + mt * 16 * (XST * 2) + k * 32);
            }
            #pragma unroll
            for (int nt = 0; nt < 3; nt++) {
                LDSM2(bh[nt], boffh + nt * 8 * (XST * 2) + k * 32);
                LDSM2(bl[nt], boffl + nt * 8 * (XST * 2) + k * 32);
            }
            #pragma unroll
            for (int mt = 0; mt < 2; mt++)
                #pragma unroll
                for (int nt = 0; nt < 3; nt++) {
                    MMA_BF16(acc[mt][nt], ah[mt], bh[nt]);
                    MMA_BF16(acc[mt][nt], ah[mt], bl[nt]);
                    MMA_BF16(acc[mt][nt], al[mt], bh[nt]);
                }
        }

        // epilogue: fp32 scratch with bias (+ q scale)
        const int g = lane >> 2, c2 = (lane & 3) * 2;
        #pragma unroll
        for (int mt = 0; mt < 2; mt++)
            #pragma unroll
            for (int nt = 0; nt < 3; nt++) {
                int col = s * 96 + nw * 24 + nt * 8 + c2;
                int buf = col / 192, ch = col - buf * 192;
                float scl = (buf == 0) ? 0.17677669529663687f : 1.0f;
                float* base = (buf == 0) ? g_q : (buf == 1) ? g_k : g_v;
                float b0 = qkvB[col], b1 = qkvB[col + 1];
                #pragma unroll
                for (int rr = 0; rr < 2; rr++) {
                    int row = mw * 32 + mt * 16 + g + rr * 8;
                    int wl_ = row >> 6, t = row & 63;
                    if (t < NT) {
                        float2 o;
                        o.x = (acc[mt][nt][rr * 2 + 0] + b0) * scl;
                        o.y = (acc[mt][nt][rr * 2 + 1] + b1) * scl;
                        *(float2*)(base + ((size_t)(pair * 2 + wl_) * NT + t) * CCH + ch) = o;
                    }
                }
            }
        __syncthreads();
    }
}

// ============================================================================
// Kernel 2: attention (per window), writes ao as bf16 splits (row-major)
// ============================================================================
constexpr int ATTN_FLOATS = 3 * NT * CPAD + 2 * SCOFF + 64;

__global__ __launch_bounds__(512, 1)
void attn_kernel(const float* __restrict__ table)
{
    extern __shared__ float smf[];
    float* qs = smf;
    float* ks = qs + NT * CPAD;
    float* vs = ks + NT * CPAD;
    float* sc = vs + NT * CPAD;
    int*   mreg = (int*)(sc + 2 * SCOFF);

    const int tid  = threadIdx.x;
    const int lane = tid & 31;
    const int warp = tid >> 5;
    const int w8   = warp & 7;
    const int half = warp >> 3;
    const int win = blockIdx.x;
    const int wy = win >> 6, wx = win & 63;

    if (tid < NT) {
        int r = tid / 7, cc = tid - (tid / 7) * 7;
        int hs = wy * 7 + r, ws = wx * 7 + cc;
        int rb = (hs >= 441) + (hs >= 445);
        int cb = (ws >= 441) + (ws >= 445);
        mreg[tid] = rb * 3 + cb;
    }
    {
        const float4* gq = (const float4*)(g_q + (size_t)win * NT * CCH);
        const float4* gk = (const float4*)(g_k + (size_t)win * NT * CCH);
        const float4* gv = (const float4*)(g_v + (size_t)win * NT * CCH);
        for (int i4 = tid; i4 < NT * 48; i4 += 512) {
            int t = i4 / 48, c4 = i4 - t * 48;
            ((float4*)(qs + t * CPAD))[c4] = gq[i4];
            ((float4*)(ks + t * CPAD))[c4] = gk[i4];
            ((float4*)(vs + t * CPAD))[c4] = gv[i4];
        }
    }
    __syncthreads();

    __nv_bfloat16* aoim = g_ao + (size_t)(win >> 1) * 2 * 128 * XST;
    const int rowbase = (win & 1) * 64;

    for (int hp = 0; hp < 3; hp++) {
        const int h  = hp * 2 + half;
        const int kb = h * HD;
        float* shc = sc + half * SCOFF;

        for (int ig = w8; ig < 13; ig += 8) {
            int i0 = ig * 4;
            float a2[4][2] = {{0,0},{0,0},{0,0},{0,0}};
            const int j2 = lane + 32;
            const bool j2v = (j2 < NT);
            #pragma unroll
            for (int d = 0; d < HD; d += 4) {
                float4 k0 = *(const float4*)(ks + lane * CPAD + kb + d);
                float4 k1 = make_float4(0.f, 0.f, 0.f, 0.f);
                if (j2v) k1 = *(const float4*)(ks + j2 * CPAD + kb + d);
                #pragma unroll
                for (int ii = 0; ii < 4; ii++) {
                    const float4 q4 = *(const float4*)(qs + (i0 + ii) * CPAD + kb + d);
                    a2[ii][0] += q4.x*k0.x + q4.y*k0.y + q4.z*k0.z + q4.w*k0.w;
                    a2[ii][1] += q4.x*k1.x + q4.y*k1.y + q4.z*k1.z + q4.w*k1.w;
                }
            }
            #pragma unroll
            for (int ii = 0; ii < 4; ii++) {
                int i = i0 + ii;
                if (i >= NT) break;
                int ri = i / 7, ci = i - ri * 7;
                int mi = mreg[i];
                #pragma unroll
                for (int jj = 0; jj < 2; jj++) {
                    int j = lane + jj * 32;
                    if (j >= NT) continue;
                    int rj = j / 7, cj = j - rj * 7;
                    int rel = (ri - rj) + (ci - cj);
                    if (rel < 0) rel += 169;
                    float bi = table[rel * NHEAD + h];
                    float msk = (mi == mreg[j]) ? 0.0f : -100.0f;
                    shc[i * SROW + j] = a2[ii][jj] + bi + msk;
                }
            }
        }
        __syncthreads();

        for (int i = w8; i < NT; i += 8) {
            float v0 = shc[i * SROW + lane];
            float v1 = (lane + 32 < NT) ? shc[i * SROW + lane + 32] : -1e30f;
            float mx = fmaxf(v0, v1);
            #pragma unroll
            for (int off = 16; off; off >>= 1)
                mx = fmaxf(mx, __shfl_xor_sync(0xffffffffu, mx, off));
            float e0 = __expf(v0 - mx);
            float e1 = (lane + 32 < NT) ? __expf(v1 - mx) : 0.0f;
            float sum = e0 + e1;
            #pragma unroll
            for (int off = 16; off; off >>= 1)
                sum += __shfl_xor_sync(0xffffffffu, sum, off);
            float inv = 1.0f / sum;
            shc[i * SROW + lane] = e0 * inv;
            if (lane + 32 < NT) shc[i * SROW + lane + 32] = e1 * inv;
        }
        __syncthreads();

        {
            const int vb = kb + lane;
            for (int ig = w8; ig < 13; ig += 8) {
                int i0 = ig * 4;
                float acc2[4] = {0.f, 0.f, 0.f, 0.f};
                #pragma unroll 4
                for (int j = 0; j < 48; j += 4) {
                    float4 p0 = *(const float4*)(shc + (i0 + 0) * SROW + j);
                    float4 p1 = *(const float4*)(shc + (i0 + 1) * SROW + j);
                    float4 p2 = *(const float4*)(shc + (i0 + 2) * SROW + j);
                    float4 p3 = *(const float4*)(shc + (i0 + 3) * SROW + j);
                    #pragma unroll
                    for (int jj = 0; jj < 4; jj++) {
                        float vv = vs[(j + jj) * CPAD + vb];
                        acc2[0] += ((const float*)&p0)[jj] * vv;
                        acc2[1] += ((const float*)&p1)[jj] * vv;
                        acc2[2] += ((const float*)&p2)[jj] * vv;
                        acc2[3] += ((const float*)&p3)[jj] * vv;
                    }
                }
                {
                    float vv = vs[48 * CPAD + vb];
                    acc2[0] += shc[(i0 + 0) * SROW + 48] * vv;
                    acc2[1] += shc[(i0 + 1) * SROW + 48] * vv;
                    acc2[2] += shc[(i0 + 2) * SROW + 48] * vv;
                    acc2[3] += shc[(i0 + 3) * SROW + 48] * vv;
                }
                #pragma unroll
                for (int ii = 0; ii < 4; ii++) {
                    if (i0 + ii < NT) {
                        __nv_bfloat16 hi, lo; bf16_split(acc2[ii], hi, lo);
                        int off = (rowbase + i0 + ii) * XST + kb + lane;
                        aoim[off] = hi;
                        aoim[128 * XST + off] = lo;
                    }
                }
            }
        }
        __syncthreads();
    }
}

// ============================================================================
// Kernel 3: proj GEMM (mma.sync) + shifted scatter
// ============================================================================
// smem: Ah 51200 | Al 51200 | Wh 38400 | Wl 38400 ; ds overlays Ah/Al (76800B)
#define PROJ_SMEM 179200

__global__ __launch_bounds__(512, 1)
void proj_kernel(const float* __restrict__ projB, float* __restrict__ out)
{
    extern __shared__ char smem[];
    __nv_bfloat16* Wh = (__nv_bfloat16*)(smem + 102400);
    __nv_bfloat16* Wl = (__nv_bfloat16*)(smem + 140800);
    float* ds = (float*)smem;
    const uint32_t sb = smem_u32(smem);
    const int tid = threadIdx.x, lane = tid & 31, warp = tid >> 5;
    const int pair = blockIdx.x;
    const int mw = warp & 3, nw = warp >> 2;

    // linear copy of both ao split images (already padded/row-major)
    {
        const uint4* s = (const uint4*)(g_ao + (size_t)pair * 2 * 128 * XST);
        uint4* d = (uint4*)smem;
        for (int i = tid; i < 6400; i += 512) d[i] = s[i];
    }
    __syncthreads();

    const uint32_t aoffh = sb +          (uint32_t)(mw * 32 + (lane & 15)) * (XST * 2) + (lane >> 4) * 16;
    const uint32_t aoffl = aoffh + 51200;
    const uint32_t boffh = sb + 102400 + (uint32_t)(nw * 24 + (lane & 7)) * (XST * 2) + ((lane >> 3) & 1) * 16;
    const uint32_t boffl = boffh + 38400;

    float acc[2][2][3][4];   // [half][mt][nt][e]
    #pragma unroll
    for (int s = 0; s < 2; s++)
        #pragma unroll
        for (int a = 0; a < 2; a++)
            #pragma unroll
            for (int b = 0; b < 3; b++)
                #pragma unroll
                for (int e = 0; e < 4; e++) acc[s][a][b][e] = 0.f;

    for (int s = 0; s < 2; s++) {
        for (int i = tid; i < 4608; i += 512) {
            int split = i >= 2304, j = i - split * 2304;
            int r = j / 24, p = j - r * 24;
            __nv_bfloat16* dst = split ? Wl : Wh;
            ((uint4*)(dst + r * XST))[p] =
                ((const uint4*)(g_projw + split * (192 * 192) + (s * 96 + r) * 192))[p];
        }
        __syncthreads();

        #pragma unroll 2
        for (int k = 0; k < 12; k++) {
            uint32_t ah[2][4], al[2][4], bh[3][2], bl[3][2];
            #pragma unroll
            for (int mt = 0; mt < 2; mt++) {
                LDSM4(ah[mt], aoffh + mt * 16 * (XST * 2) + k * 32);
                LDSM4(al[mt], aoffl + mt * 16 * (XST * 2) + k * 32);
            }
            #pragma unroll
            for (int nt = 0; nt < 3; nt++) {
                LDSM2(bh[nt], boffh + nt * 8 * (XST * 2) + k * 32);
                LDSM2(bl[nt], boffl + nt * 8 * (XST * 2) + k * 32);
            }
            #pragma unroll
            for (int mt = 0; mt < 2; mt++)
                #pragma unroll
                for (int nt = 0; nt < 3; nt++) {
                    MMA_BF16(acc[s][mt][nt], ah[mt], bh[nt]);
                    MMA_BF16(acc[s][mt][nt], ah[mt], bl[nt]);
                    MMA_BF16(acc[s][mt][nt], al[mt], bh[nt]);
                }
        }
        __syncthreads();
    }

    // write accums into ds[c][tok2] (+bias); ds overlays A region (A dead now)
    {
        const int g = lane >> 2, c2 = (lane & 3) * 2;
        #pragma unroll
        for (int s = 0; s < 2; s++)
            #pragma unroll
            for (int mt = 0; mt < 2; mt++)
                #pragma unroll
                for (int nt = 0; nt < 3; nt++) {
                    int col = s * 96 + nw * 24 + nt * 8 + c2;
                    float b0 = projB[col], b1 = projB[col + 1];
                    #pragma unroll
                    for (int rr = 0; rr < 2; rr++) {
                        int row = mw * 32 + mt * 16 + g + rr * 8;
                        int wl_ = row >> 6, t = row & 63;
                        if (t < NT) {
                            int tt = wl_ * 49 + t;
                            ds[col * 100 + tt]       = acc[s][mt][nt][rr * 2 + 0] + b0;
                            ds[(col + 1) * 100 + tt] = acc[s][mt][nt][rr * 2 + 1] + b1;
                        }
                    }
                }
    }
    __syncthreads();

    // scatter with reverse shift (coalesced along w)
    for (int idx = tid; idx < CCH * 98; idx += 512) {
        int c = idx / 98, tt = idx - c * 98;
        int wl_ = tt / 49, t = tt - wl_ * 49;
        int win = pair * 2 + wl_, wy = win >> 6, wx = win & 63;
        int r = t / 7, cc = t - r * 7;
        int h = wy * 7 + r + 3; if (h >= HDIM) h -= HDIM;
        int w = wx * 7 + cc + 3; if (w >= HDIM) w -= HDIM;
        out[c * HWSZ + h * HDIM + w] = ds[c * 100 + tt];
    }
}

// ============================================================================
extern "C" void kernel_launch(void* const* d_in, const int* in_sizes, int n_in,
                              void* d_out, int out_size) {
    const float* x     = (const float*)d_in[0];
    const float* qkvB  = (const float*)d_in[2];
    const float* qkvW  = (const float*)d_in[1];
    const float* projW = (const float*)d_in[3];
    const float* projB = (const float*)d_in[4];
    const float* table = (const float*)d_in[5];
    float* out = (float*)d_out;

    cudaFuncSetAttribute(qkv_kernel,  cudaFuncAttributeMaxDynamicSharedMemorySize, QKV_SMEM);
    cudaFuncSetAttribute(proj_kernel, cudaFuncAttributeMaxDynamicSharedMemorySize, PROJ_SMEM);
    cudaFuncSetAttribute(attn_kernel, cudaFuncAttributeMaxDynamicSharedMemorySize, ATTN_FLOATS * 4);

    prep_kernel<<<576, 256>>>(qkvW, projW);
    qkv_kernel<<<NPAIR, 512, QKV_SMEM>>>(x, qkvB);
    attn_kernel<<<NWIN, 512, ATTN_FLOATS * 4>>>(table);
    proj_kernel<<<NPAIR, 512, PROJ_SMEM>>>(projB, out);
}